// round 10
// baseline (speedup 1.0000x reference)
#include <cuda_runtime.h>
#include <math.h>

#define NN    50000
#define EE    400000
#define ETOT  (NN + EE)
#define CH    256           // channels (HEADS*HID and OUT)
#define KIN   20
#define NEG_SLOPE 0.2f
#define EPSS  1e-16f

// ---------------- scratch (static device globals; no allocations) ----------
__device__ float g_xl1[NN * CH];
__device__ float g_xr1[NN * CH];
__device__ float g_h[NN * CH];      // ELU(layer-1 output)
__device__ float g_xl2[NN * CH];
__device__ float g_xr2[NN * CH];
__device__ int   g_deg[NN];         // degree counts, then scatter cursor
__device__ int   g_off[NN + 1];     // CSR offsets
__device__ int   g_csr_src[ETOT];

__device__ __forceinline__ float lrelu(float v) {
    return v > 0.0f ? v : NEG_SLOPE * v;
}

// ---- packed f32x2 (FFMA2) helpers ----
__device__ __forceinline__ unsigned long long pack2(float lo, float hi) {
    unsigned long long r;
    asm("mov.b64 %0, {%1, %2};" : "=l"(r) : "f"(lo), "f"(hi));
    return r;
}
__device__ __forceinline__ unsigned long long fma2(unsigned long long a,
                                                   unsigned long long b,
                                                   unsigned long long c) {
    unsigned long long d;
    asm("fma.rn.f32x2 %0, %1, %2, %3;" : "=l"(d) : "l"(a), "l"(b), "l"(c));
    return d;
}
__device__ __forceinline__ float2 unpack2(unsigned long long v) {
    float lo, hi;
    asm("mov.b64 {%0, %1}, %2;" : "=f"(lo), "=f"(hi) : "l"(v));
    return make_float2(lo, hi);
}

// ================= CSR construction =================
__global__ void zero_deg() {
    int i = blockIdx.x * blockDim.x + threadIdx.x;
    if (i < NN) g_deg[i] = 0;
}

__global__ void csr_count(const int* __restrict__ ei) {
    int e = blockIdx.x * blockDim.x + threadIdx.x;
    if (e >= ETOT) return;
    int dst = (e < EE) ? ei[EE + e] : e - EE;
    atomicAdd(&g_deg[dst], 1);
}

// single-block exclusive scan over g_deg -> g_off; also zeroes g_deg (cursor)
__global__ void csr_scan() {
    int tid = threadIdx.x;
    int lane = tid & 31, wid = tid >> 5;
    __shared__ int wsum[32];
    __shared__ int carry_s;
    if (tid == 0) carry_s = 0;
    __syncthreads();
    for (int base = 0; base < NN; base += 1024) {
        __syncthreads();
        int i = base + tid;
        int v = (i < NN) ? g_deg[i] : 0;
        if (i < NN) g_deg[i] = 0;
        int x = v;
        #pragma unroll
        for (int o = 1; o < 32; o <<= 1) {
            int y = __shfl_up_sync(0xffffffffu, x, o);
            if (lane >= o) x += y;
        }
        if (lane == 31) wsum[wid] = x;
        __syncthreads();
        if (wid == 0) {
            int w = wsum[lane];
            #pragma unroll
            for (int o = 1; o < 32; o <<= 1) {
                int y = __shfl_up_sync(0xffffffffu, w, o);
                if (lane >= o) w += y;
            }
            wsum[lane] = w;
        }
        __syncthreads();
        int blockincl = x + (wid > 0 ? wsum[wid - 1] : 0);
        int excl = carry_s + blockincl - v;
        if (i < NN) g_off[i] = excl;
        __syncthreads();
        if (tid == 1023) carry_s += blockincl;
    }
    __syncthreads();
    if (tid == 0) g_off[NN] = carry_s;
}

__global__ void csr_scatter(const int* __restrict__ ei) {
    int e = blockIdx.x * blockDim.x + threadIdx.x;
    if (e >= ETOT) return;
    int src, dst;
    if (e < EE) { src = ei[e]; dst = ei[EE + e]; }
    else        { src = dst = e - EE; }
    int pos = g_off[dst] + atomicAdd(&g_deg[dst], 1);
    g_csr_src[pos] = src;
}

// ================= layer-1 GEMM: x[N,20]@W[20,256]+b, 64 rows/block ========
__global__ void gemm1_kernel(const float* __restrict__ x,
                             const float* __restrict__ Wl, const float* __restrict__ bl,
                             const float* __restrict__ Wr, const float* __restrict__ br) {
    __shared__ float swl[KIN * 256];
    __shared__ float swr[KIN * 256];
    __shared__ float sx[64][KIN];
    int tid = threadIdx.x;
    for (int i = tid; i < KIN * 256; i += 256) { swl[i] = Wl[i]; swr[i] = Wr[i]; }
    int nb = blockIdx.x * 64;
    for (int i = tid; i < 64 * KIN; i += 256) {
        int node = nb + i / KIN;
        sx[i / KIN][i % KIN] = (node < NN) ? x[node * KIN + (i % KIN)] : 0.0f;
    }
    __syncthreads();
    float bL = bl[tid], bR = br[tid];
    #pragma unroll 4
    for (int i = 0; i < 64; i++) {
        int node = nb + i;
        if (node >= NN) break;
        float al = bL, ar = bR;
        #pragma unroll
        for (int k = 0; k < KIN; k++) {
            float xv = sx[i][k];
            al = fmaf(xv, swl[k * 256 + tid], al);
            ar = fmaf(xv, swr[k * 256 + tid], ar);
        }
        g_xl1[node * 256 + tid] = al;
        g_xr1[node * 256 + tid] = ar;
    }
}

// ================= dual layer-2 GEMM, 128x64 tile, 8x4x2 per thread =========
__global__ void __launch_bounds__(256, 2)
gemm_dual(const float* __restrict__ Wl, const float* __restrict__ bl,
          const float* __restrict__ Wr, const float* __restrict__ br) {
    const float* __restrict__ A = g_h;
    __shared__ float As[16][128];
    __shared__ float Bl[16][64];
    __shared__ float Br[16][64];
    int tid = threadIdx.x;
    int tx = tid & 15;
    int ty = tid >> 4;
    int row0 = blockIdx.x * 128;
    int col0 = blockIdx.y * 64;

    unsigned long long accL[8][2], accR[8][2];
    #pragma unroll
    for (int i = 0; i < 8; i++) {
        accL[i][0] = 0ull; accL[i][1] = 0ull;
        accR[i][0] = 0ull; accR[i][1] = 0ull;
    }

    for (int kt = 0; kt < 256; kt += 16) {
        #pragma unroll
        for (int j = 0; j < 8; j++) {
            int i = tid + j * 256;
            int m = i >> 4, k = i & 15;
            int row = row0 + m;
            As[k][m] = (row < NN) ? A[row * 256 + kt + k] : 0.0f;
        }
        #pragma unroll
        for (int j = 0; j < 4; j++) {
            int i = tid + j * 256;
            int k = i >> 6, col = i & 63;
            Bl[k][col] = Wl[(kt + k) * 256 + col0 + col];
            Br[k][col] = Wr[(kt + k) * 256 + col0 + col];
        }
        __syncthreads();
        #pragma unroll
        for (int k = 0; k < 16; k++) {
            float4 a0 = *(const float4*)&As[k][ty * 8];
            float4 a1 = *(const float4*)&As[k][ty * 8 + 4];
            ulonglong2 b  = *(const ulonglong2*)&Bl[k][tx * 4];
            ulonglong2 b2 = *(const ulonglong2*)&Br[k][tx * 4];
            unsigned long long ap[8];
            ap[0] = pack2(a0.x, a0.x); ap[1] = pack2(a0.y, a0.y);
            ap[2] = pack2(a0.z, a0.z); ap[3] = pack2(a0.w, a0.w);
            ap[4] = pack2(a1.x, a1.x); ap[5] = pack2(a1.y, a1.y);
            ap[6] = pack2(a1.z, a1.z); ap[7] = pack2(a1.w, a1.w);
            #pragma unroll
            for (int i = 0; i < 8; i++) {
                accL[i][0] = fma2(ap[i], b.x,  accL[i][0]);
                accL[i][1] = fma2(ap[i], b.y,  accL[i][1]);
                accR[i][0] = fma2(ap[i], b2.x, accR[i][0]);
                accR[i][1] = fma2(ap[i], b2.y, accR[i][1]);
            }
        }
        __syncthreads();
    }
    #pragma unroll
    for (int i = 0; i < 8; i++) {
        int row = row0 + ty * 8 + i;
        if (row >= NN) continue;
        int col = col0 + tx * 4;
        float2 l0 = unpack2(accL[i][0]), l1 = unpack2(accL[i][1]);
        float2 r0 = unpack2(accR[i][0]), r1 = unpack2(accR[i][1]);
        float4 vl, vr;
        vl.x = l0.x + bl[col + 0]; vl.y = l0.y + bl[col + 1];
        vl.z = l1.x + bl[col + 2]; vl.w = l1.y + bl[col + 3];
        vr.x = r0.x + br[col + 0]; vr.y = r0.y + br[col + 1];
        vr.z = r1.x + br[col + 2]; vr.w = r1.y + br[col + 3];
        *(float4*)&g_xl2[row * 256 + col] = vl;
        *(float4*)&g_xr2[row * 256 + col] = vr;
    }
}

// ================= fused edge pass: 4-edge ILP online softmax ===============
// Warp per node, lane owns 8 channels. 4 edges per iteration, prefetch depth 4,
// interleaved butterfly SHFL reductions (4 independent chains share latency),
// one rescale per chunk.
template<int LAYER>
__global__ void __launch_bounds__(256, 2)
fused_edge(const float* __restrict__ att,
           const float* __restrict__ bias,
           float* __restrict__ out_arg) {
    const float* __restrict__ xl = (LAYER == 1) ? g_xl1 : g_xl2;
    const float* __restrict__ xr = (LAYER == 1) ? g_xr1 : g_xr2;

    int node = (blockIdx.x * blockDim.x + threadIdx.x) >> 5;
    int lane = threadIdx.x & 31;
    if (node >= NN) return;
    int s0 = g_off[node], s1 = g_off[node + 1];
    int c = lane * 8;

    const float4* pr = (const float4*)(xr + node * CH + c);
    float4 r0 = pr[0], r1 = pr[1];
    const float4* pa = (const float4*)(att + c);
    float4 w0 = pa[0], w1 = pa[1];

    float m = -INFINITY, ssum = 0.0f;
    float4 acc0 = make_float4(0.f, 0.f, 0.f, 0.f);
    float4 acc1 = make_float4(0.f, 0.f, 0.f, 0.f);

    float4 Xa[4], Xb[4];
    float4 z4 = make_float4(0.f, 0.f, 0.f, 0.f);
    #pragma unroll
    for (int j = 0; j < 4; j++) { Xa[j] = z4; Xb[j] = z4; }
    // prologue: load first chunk (up to 4 edges)
    #pragma unroll
    for (int j = 0; j < 4; j++) {
        if (s0 + j < s1) {
            const float4* p = (const float4*)(xl + g_csr_src[s0 + j] * CH + c);
            Xa[j] = p[0]; Xb[j] = p[1];
        }
    }

    for (int base = s0; base < s1; base += 4) {
        int rem = s1 - base;                 // >= 1
        float4 Ca[4], Cb[4];
        #pragma unroll
        for (int j = 0; j < 4; j++) { Ca[j] = Xa[j]; Cb[j] = Xb[j]; }
        // prefetch next chunk
        #pragma unroll
        for (int j = 0; j < 4; j++) {
            if (base + 4 + j < s1) {
                const float4* p = (const float4*)(xl + g_csr_src[base + 4 + j] * CH + c);
                Xa[j] = p[0]; Xb[j] = p[1];
            }
        }
        // 4 independent logit chains
        float p[4];
        #pragma unroll
        for (int j = 0; j < 4; j++) {
            float q;
            q  =        w0.x * lrelu(Ca[j].x + r0.x);
            q = fmaf(w0.y, lrelu(Ca[j].y + r0.y), q);
            q = fmaf(w0.z, lrelu(Ca[j].z + r0.z), q);
            q = fmaf(w0.w, lrelu(Ca[j].w + r0.w), q);
            q = fmaf(w1.x, lrelu(Cb[j].x + r1.x), q);
            q = fmaf(w1.y, lrelu(Cb[j].y + r1.y), q);
            q = fmaf(w1.z, lrelu(Cb[j].z + r1.z), q);
            q = fmaf(w1.w, lrelu(Cb[j].w + r1.w), q);
            p[j] = q;
        }
        // interleaved butterfly reductions: 4 chains share each level's latency
        #pragma unroll
        for (int off = (LAYER == 1 ? 4 : 16); off > 0; off >>= 1) {
            #pragma unroll
            for (int j = 0; j < 4; j++)
                p[j] += __shfl_xor_sync(0xffffffffu, p[j], off);
        }
        #pragma unroll
        for (int j = 0; j < 4; j++)
            if (j >= rem) p[j] = -INFINITY;
        // merged online-softmax update (one rescale per chunk)
        float mp = fmaxf(fmaxf(p[0], p[1]), fmaxf(p[2], p[3]));
        if (mp > m) {
            float sc = __expf(m - mp);       // exp(-inf)=0 on first chunk
            ssum *= sc;
            acc0.x *= sc; acc0.y *= sc; acc0.z *= sc; acc0.w *= sc;
            acc1.x *= sc; acc1.y *= sc; acc1.z *= sc; acc1.w *= sc;
            m = mp;
        }
        #pragma unroll
        for (int j = 0; j < 4; j++) {
            if (j < rem) {
                float wj = __expf(p[j] - m);
                ssum += wj;
                acc0.x = fmaf(wj, Ca[j].x, acc0.x);
                acc0.y = fmaf(wj, Ca[j].y, acc0.y);
                acc0.z = fmaf(wj, Ca[j].z, acc0.z);
                acc0.w = fmaf(wj, Ca[j].w, acc0.w);
                acc1.x = fmaf(wj, Cb[j].x, acc1.x);
                acc1.y = fmaf(wj, Cb[j].y, acc1.y);
                acc1.z = fmaf(wj, Cb[j].z, acc1.z);
                acc1.w = fmaf(wj, Cb[j].w, acc1.w);
            }
        }
    }

    float inv = 1.0f / (ssum + EPSS);
    const float4* pb = (const float4*)(bias + c);
    float4 b0 = pb[0], b1 = pb[1];
    float v[8] = { acc0.x * inv + b0.x, acc0.y * inv + b0.y,
                   acc0.z * inv + b0.z, acc0.w * inv + b0.w,
                   acc1.x * inv + b1.x, acc1.y * inv + b1.y,
                   acc1.z * inv + b1.z, acc1.w * inv + b1.w };
    if (LAYER == 1) {
        #pragma unroll
        for (int j = 0; j < 8; j++) v[j] = v[j] > 0.0f ? v[j] : expm1f(v[j]);
    }
    float* outp = (LAYER == 1) ? g_h : out_arg;
    float4* po = (float4*)(outp + node * CH + c);
    po[0] = make_float4(v[0], v[1], v[2], v[3]);
    po[1] = make_float4(v[4], v[5], v[6], v[7]);
}

// ================= launcher =================================================
extern "C" void kernel_launch(void* const* d_in, const int* in_sizes, int n_in,
                              void* d_out, int out_size) {
    const float* x     = (const float*)d_in[0];
    const int*   ei    = (const int*)  d_in[1];
    const float* W_l1  = (const float*)d_in[2];
    const float* b_l1  = (const float*)d_in[3];
    const float* W_r1  = (const float*)d_in[4];
    const float* b_r1  = (const float*)d_in[5];
    const float* att1  = (const float*)d_in[6];
    const float* bias1 = (const float*)d_in[7];
    const float* W_l2  = (const float*)d_in[8];
    const float* b_l2  = (const float*)d_in[9];
    const float* W_r2  = (const float*)d_in[10];
    const float* b_r2  = (const float*)d_in[11];
    const float* att2  = (const float*)d_in[12];
    const float* bias2 = (const float*)d_in[13];
    float* out = (float*)d_out;

    const int T = 256;
    int blkN    = (NN + T - 1) / T;
    int blkE    = (ETOT + T - 1) / T;
    int blkNode = (NN + 7) / 8;        // warp per node
    int blkG1   = (NN + 63) / 64;

    // CSR build
    zero_deg<<<blkN, T>>>();
    csr_count<<<blkE, T>>>(ei);
    csr_scan<<<1, 1024>>>();
    csr_scatter<<<blkE, T>>>(ei);

    // layer 1
    gemm1_kernel<<<blkG1, T>>>(x, W_l1, b_l1, W_r1, b_r1);
    fused_edge<1><<<blkNode, T>>>(att1, bias1, nullptr);

    // layer 2
    dim3 g2((NN + 127) / 128, 4);
    gemm_dual<<<g2, T>>>(W_l2, b_l2, W_r2, b_r2);
    fused_edge<2><<<blkNode, T>>>(att2, bias2, out);
}

// round 11
// speedup vs baseline: 1.0908x; 1.0908x over previous
#include <cuda_runtime.h>
#include <math.h>

#define NN    50000
#define EE    400000
#define ETOT  (NN + EE)
#define CH    256           // channels (HEADS*HID and OUT)
#define KIN   20
#define NEG_SLOPE 0.2f
#define EPSS  1e-16f

// ---------------- scratch (static device globals; no allocations) ----------
__device__ float g_xl1[NN * CH];
__device__ float g_xr1[NN * CH];
__device__ float g_h[NN * CH];      // ELU(layer-1 output)
__device__ float g_xl2[NN * CH];
__device__ float g_xr2[NN * CH];
__device__ int   g_deg[NN];         // degree counts, then scatter cursor
__device__ int   g_off[NN + 1];     // CSR offsets
__device__ int   g_part[64];        // scan block partials
__device__ int   g_csr_src[ETOT];

__device__ __forceinline__ float lrelu(float v) {
    return v > 0.0f ? v : NEG_SLOPE * v;
}

// ---- packed f32x2 (FFMA2) helpers ----
__device__ __forceinline__ unsigned long long pack2(float lo, float hi) {
    unsigned long long r;
    asm("mov.b64 %0, {%1, %2};" : "=l"(r) : "f"(lo), "f"(hi));
    return r;
}
__device__ __forceinline__ unsigned long long fma2(unsigned long long a,
                                                   unsigned long long b,
                                                   unsigned long long c) {
    unsigned long long d;
    asm("fma.rn.f32x2 %0, %1, %2, %3;" : "=l"(d) : "l"(a), "l"(b), "l"(c));
    return d;
}
__device__ __forceinline__ float2 unpack2(unsigned long long v) {
    float lo, hi;
    asm("mov.b64 {%0, %1}, %2;" : "=f"(lo), "=f"(hi) : "l"(v));
    return make_float2(lo, hi);
}

// ================= CSR construction =================
__global__ void zero_deg() {
    int i = blockIdx.x * blockDim.x + threadIdx.x;
    if (i < NN) g_deg[i] = 0;
}

__global__ void csr_count(const int* __restrict__ ei) {
    int e = blockIdx.x * blockDim.x + threadIdx.x;
    if (e >= ETOT) return;
    int dst = (e < EE) ? ei[EE + e] : e - EE;
    atomicAdd(&g_deg[dst], 1);
}

// ---- 3-kernel exclusive scan of g_deg -> g_off (also zeroes g_deg) ----
__global__ void scan1() {
    int tid = threadIdx.x;
    int lane = tid & 31, wid = tid >> 5;
    __shared__ int wsum[32];
    int i = blockIdx.x * 1024 + tid;
    int v = (i < NN) ? g_deg[i] : 0;
    if (i < NN) g_deg[i] = 0;
    int x = v;
    #pragma unroll
    for (int o = 1; o < 32; o <<= 1) {
        int y = __shfl_up_sync(0xffffffffu, x, o);
        if (lane >= o) x += y;
    }
    if (lane == 31) wsum[wid] = x;
    __syncthreads();
    if (wid == 0) {
        int w = wsum[lane];
        #pragma unroll
        for (int o = 1; o < 32; o <<= 1) {
            int y = __shfl_up_sync(0xffffffffu, w, o);
            if (lane >= o) w += y;
        }
        wsum[lane] = w;
    }
    __syncthreads();
    int incl = x + (wid > 0 ? wsum[wid - 1] : 0);
    if (i < NN) g_off[i] = incl - v;     // in-block exclusive
    if (tid == 1023) g_part[blockIdx.x] = incl;  // block total
}

__global__ void scan2(int nblk) {
    __shared__ int sp[64];
    int t = threadIdx.x;
    sp[t] = (t < nblk) ? g_part[t] : 0;
    __syncthreads();
    if (t == 0) {
        int run = 0;
        for (int i = 0; i < nblk; i++) { int tmp = sp[i]; sp[i] = run; run += tmp; }
    }
    __syncthreads();
    if (t < nblk) g_part[t] = sp[t];
}

__global__ void scan3() {
    int i = blockIdx.x * 1024 + threadIdx.x;
    if (i < NN) g_off[i] += g_part[blockIdx.x];
    if (i == 0) g_off[NN] = ETOT;
}

__global__ void csr_scatter(const int* __restrict__ ei) {
    int e = blockIdx.x * blockDim.x + threadIdx.x;
    if (e >= ETOT) return;
    int src, dst;
    if (e < EE) { src = ei[e]; dst = ei[EE + e]; }
    else        { src = dst = e - EE; }
    int pos = g_off[dst] + atomicAdd(&g_deg[dst], 1);
    g_csr_src[pos] = src;
}

// ================= layer-1 GEMM: x[N,20]@W[20,256]+b, 64 rows/block ========
__global__ void gemm1_kernel(const float* __restrict__ x,
                             const float* __restrict__ Wl, const float* __restrict__ bl,
                             const float* __restrict__ Wr, const float* __restrict__ br) {
    __shared__ float swl[KIN * 256];
    __shared__ float swr[KIN * 256];
    __shared__ float sx[64][KIN];
    int tid = threadIdx.x;
    for (int i = tid; i < KIN * 256; i += 256) { swl[i] = Wl[i]; swr[i] = Wr[i]; }
    int nb = blockIdx.x * 64;
    for (int i = tid; i < 64 * KIN; i += 256) {
        int node = nb + i / KIN;
        sx[i / KIN][i % KIN] = (node < NN) ? x[node * KIN + (i % KIN)] : 0.0f;
    }
    __syncthreads();
    float bL = bl[tid], bR = br[tid];
    #pragma unroll 4
    for (int i = 0; i < 64; i++) {
        int node = nb + i;
        if (node >= NN) break;
        float al = bL, ar = bR;
        #pragma unroll
        for (int k = 0; k < KIN; k++) {
            float xv = sx[i][k];
            al = fmaf(xv, swl[k * 256 + tid], al);
            ar = fmaf(xv, swr[k * 256 + tid], ar);
        }
        g_xl1[node * 256 + tid] = al;
        g_xr1[node * 256 + tid] = ar;
    }
}

// ================= dual layer-2 GEMM, 128x64 tile, 8x4x2 per thread =========
__global__ void __launch_bounds__(256, 2)
gemm_dual(const float* __restrict__ Wl, const float* __restrict__ bl,
          const float* __restrict__ Wr, const float* __restrict__ br) {
    const float* __restrict__ A = g_h;
    __shared__ float As[16][128];
    __shared__ float Bl[16][64];
    __shared__ float Br[16][64];
    int tid = threadIdx.x;
    int tx = tid & 15;
    int ty = tid >> 4;
    int row0 = blockIdx.x * 128;
    int col0 = blockIdx.y * 64;

    unsigned long long accL[8][2], accR[8][2];
    #pragma unroll
    for (int i = 0; i < 8; i++) {
        accL[i][0] = 0ull; accL[i][1] = 0ull;
        accR[i][0] = 0ull; accR[i][1] = 0ull;
    }

    for (int kt = 0; kt < 256; kt += 16) {
        #pragma unroll
        for (int j = 0; j < 8; j++) {
            int i = tid + j * 256;
            int m = i >> 4, k = i & 15;
            int row = row0 + m;
            As[k][m] = (row < NN) ? A[row * 256 + kt + k] : 0.0f;
        }
        #pragma unroll
        for (int j = 0; j < 4; j++) {
            int i = tid + j * 256;
            int k = i >> 6, col = i & 63;
            Bl[k][col] = Wl[(kt + k) * 256 + col0 + col];
            Br[k][col] = Wr[(kt + k) * 256 + col0 + col];
        }
        __syncthreads();
        #pragma unroll
        for (int k = 0; k < 16; k++) {
            float4 a0 = *(const float4*)&As[k][ty * 8];
            float4 a1 = *(const float4*)&As[k][ty * 8 + 4];
            ulonglong2 b  = *(const ulonglong2*)&Bl[k][tx * 4];
            ulonglong2 b2 = *(const ulonglong2*)&Br[k][tx * 4];
            unsigned long long ap[8];
            ap[0] = pack2(a0.x, a0.x); ap[1] = pack2(a0.y, a0.y);
            ap[2] = pack2(a0.z, a0.z); ap[3] = pack2(a0.w, a0.w);
            ap[4] = pack2(a1.x, a1.x); ap[5] = pack2(a1.y, a1.y);
            ap[6] = pack2(a1.z, a1.z); ap[7] = pack2(a1.w, a1.w);
            #pragma unroll
            for (int i = 0; i < 8; i++) {
                accL[i][0] = fma2(ap[i], b.x,  accL[i][0]);
                accL[i][1] = fma2(ap[i], b.y,  accL[i][1]);
                accR[i][0] = fma2(ap[i], b2.x, accR[i][0]);
                accR[i][1] = fma2(ap[i], b2.y, accR[i][1]);
            }
        }
        __syncthreads();
    }
    #pragma unroll
    for (int i = 0; i < 8; i++) {
        int row = row0 + ty * 8 + i;
        if (row >= NN) continue;
        int col = col0 + tx * 4;
        float2 l0 = unpack2(accL[i][0]), l1 = unpack2(accL[i][1]);
        float2 r0 = unpack2(accR[i][0]), r1 = unpack2(accR[i][1]);
        float4 vl, vr;
        vl.x = l0.x + bl[col + 0]; vl.y = l0.y + bl[col + 1];
        vl.z = l1.x + bl[col + 2]; vl.w = l1.y + bl[col + 3];
        vr.x = r0.x + br[col + 0]; vr.y = r0.y + br[col + 1];
        vr.z = r1.x + br[col + 2]; vr.w = r1.y + br[col + 3];
        *(float4*)&g_xl2[row * 256 + col] = vl;
        *(float4*)&g_xr2[row * 256 + col] = vr;
    }
}

// ================= fused edge pass: 2 warps/node, 2-edge pipeline ===========
// 256 threads = 8 warps = 4 nodes per block (50000 % 4 == 0 -> full blocks).
// Each warp runs an online softmax over half the node's edges; the two
// halves merge once via shared memory.
template<int LAYER>
__global__ void fused_edge(const float* __restrict__ att,
                           const float* __restrict__ bias,
                           float* __restrict__ out_arg) {
    const float* __restrict__ xl = (LAYER == 1) ? g_xl1 : g_xl2;
    const float* __restrict__ xr = (LAYER == 1) ? g_xr1 : g_xr2;

    __shared__ float4 sAcc[4][32][2];
    __shared__ float  sM[4][32];
    __shared__ float  sS[4][32];

    int tid  = threadIdx.x;
    int lane = tid & 31;
    int nslot = tid >> 6;               // 0..3: node slot in block
    int half  = (tid >> 5) & 1;         // 0 or 1: which edge half
    int node  = blockIdx.x * 4 + nslot;
    int s0 = g_off[node], s1 = g_off[node + 1];
    int mid = s0 + ((s1 - s0 + 1) >> 1);
    int a0 = half ? mid : s0;
    int a1 = half ? s1  : mid;
    int c = lane * 8;

    const float4* pr = (const float4*)(xr + node * CH + c);
    float4 r0 = pr[0], r1 = pr[1];
    const float4* pa = (const float4*)(att + c);
    float4 w0 = pa[0], w1 = pa[1];

    float m = -INFINITY, ssum = 0.0f;
    float4 acc0 = make_float4(0.f, 0.f, 0.f, 0.f);
    float4 acc1 = make_float4(0.f, 0.f, 0.f, 0.f);

    if (a0 < a1) {
        // prologue: prefetch edges a0 (A) and a0+1 (B)
        float4 A0, A1, B0, B1;
        {
            const float4* p = (const float4*)(xl + g_csr_src[a0] * CH + c);
            A0 = p[0]; A1 = p[1];
        }
        if (a0 + 1 < a1) {
            const float4* p = (const float4*)(xl + g_csr_src[a0 + 1] * CH + c);
            B0 = p[0]; B1 = p[1];
        }
        int s = a0;
        for (; s + 1 < a1; s += 2) {
            float4 c0 = A0, c1 = A1, d0 = B0, d1 = B1;
            if (s + 2 < a1) {
                const float4* p = (const float4*)(xl + g_csr_src[s + 2] * CH + c);
                A0 = p[0]; A1 = p[1];
            }
            if (s + 3 < a1) {
                const float4* p = (const float4*)(xl + g_csr_src[s + 3] * CH + c);
                B0 = p[0]; B1 = p[1];
            }
            float p1, p2;
            p1  =        w0.x * lrelu(c0.x + r0.x);
            p2  =        w0.x * lrelu(d0.x + r0.x);
            p1 = fmaf(w0.y, lrelu(c0.y + r0.y), p1);
            p2 = fmaf(w0.y, lrelu(d0.y + r0.y), p2);
            p1 = fmaf(w0.z, lrelu(c0.z + r0.z), p1);
            p2 = fmaf(w0.z, lrelu(d0.z + r0.z), p2);
            p1 = fmaf(w0.w, lrelu(c0.w + r0.w), p1);
            p2 = fmaf(w0.w, lrelu(d0.w + r0.w), p2);
            p1 = fmaf(w1.x, lrelu(c1.x + r1.x), p1);
            p2 = fmaf(w1.x, lrelu(d1.x + r1.x), p2);
            p1 = fmaf(w1.y, lrelu(c1.y + r1.y), p1);
            p2 = fmaf(w1.y, lrelu(d1.y + r1.y), p2);
            p1 = fmaf(w1.z, lrelu(c1.z + r1.z), p1);
            p2 = fmaf(w1.z, lrelu(d1.z + r1.z), p2);
            p1 = fmaf(w1.w, lrelu(c1.w + r1.w), p1);
            p2 = fmaf(w1.w, lrelu(d1.w + r1.w), p2);
            if (LAYER == 1) {
                p1 += __shfl_xor_sync(0xffffffffu, p1, 4);
                p2 += __shfl_xor_sync(0xffffffffu, p2, 4);
                p1 += __shfl_xor_sync(0xffffffffu, p1, 2);
                p2 += __shfl_xor_sync(0xffffffffu, p2, 2);
                p1 += __shfl_xor_sync(0xffffffffu, p1, 1);
                p2 += __shfl_xor_sync(0xffffffffu, p2, 1);
            } else {
                #pragma unroll
                for (int off = 16; off > 0; off >>= 1) {
                    p1 += __shfl_xor_sync(0xffffffffu, p1, off);
                    p2 += __shfl_xor_sync(0xffffffffu, p2, off);
                }
            }
            float mp = fmaxf(p1, p2);
            if (mp > m) {
                float sc = __expf(m - mp);
                ssum *= sc;
                acc0.x *= sc; acc0.y *= sc; acc0.z *= sc; acc0.w *= sc;
                acc1.x *= sc; acc1.y *= sc; acc1.z *= sc; acc1.w *= sc;
                m = mp;
            }
            float wp = __expf(p1 - m);
            float wq = __expf(p2 - m);
            ssum += wp + wq;
            acc0.x = fmaf(wp, c0.x, fmaf(wq, d0.x, acc0.x));
            acc0.y = fmaf(wp, c0.y, fmaf(wq, d0.y, acc0.y));
            acc0.z = fmaf(wp, c0.z, fmaf(wq, d0.z, acc0.z));
            acc0.w = fmaf(wp, c0.w, fmaf(wq, d0.w, acc0.w));
            acc1.x = fmaf(wp, c1.x, fmaf(wq, d1.x, acc1.x));
            acc1.y = fmaf(wp, c1.y, fmaf(wq, d1.y, acc1.y));
            acc1.z = fmaf(wp, c1.z, fmaf(wq, d1.z, acc1.z));
            acc1.w = fmaf(wp, c1.w, fmaf(wq, d1.w, acc1.w));
        }
        if (s < a1) {   // tail
            float4 c0 = A0, c1 = A1;
            float p1;
            p1  =        w0.x * lrelu(c0.x + r0.x);
            p1 = fmaf(w0.y, lrelu(c0.y + r0.y), p1);
            p1 = fmaf(w0.z, lrelu(c0.z + r0.z), p1);
            p1 = fmaf(w0.w, lrelu(c0.w + r0.w), p1);
            p1 = fmaf(w1.x, lrelu(c1.x + r1.x), p1);
            p1 = fmaf(w1.y, lrelu(c1.y + r1.y), p1);
            p1 = fmaf(w1.z, lrelu(c1.z + r1.z), p1);
            p1 = fmaf(w1.w, lrelu(c1.w + r1.w), p1);
            if (LAYER == 1) {
                p1 += __shfl_xor_sync(0xffffffffu, p1, 4);
                p1 += __shfl_xor_sync(0xffffffffu, p1, 2);
                p1 += __shfl_xor_sync(0xffffffffu, p1, 1);
            } else {
                #pragma unroll
                for (int off = 16; off > 0; off >>= 1)
                    p1 += __shfl_xor_sync(0xffffffffu, p1, off);
            }
            if (p1 > m) {
                float sc = __expf(m - p1);
                ssum *= sc;
                acc0.x *= sc; acc0.y *= sc; acc0.z *= sc; acc0.w *= sc;
                acc1.x *= sc; acc1.y *= sc; acc1.z *= sc; acc1.w *= sc;
                m = p1;
            }
            float wp = __expf(p1 - m);
            ssum += wp;
            acc0.x = fmaf(wp, c0.x, acc0.x); acc0.y = fmaf(wp, c0.y, acc0.y);
            acc0.z = fmaf(wp, c0.z, acc0.z); acc0.w = fmaf(wp, c0.w, acc0.w);
            acc1.x = fmaf(wp, c1.x, acc1.x); acc1.y = fmaf(wp, c1.y, acc1.y);
            acc1.z = fmaf(wp, c1.z, acc1.z); acc1.w = fmaf(wp, c1.w, acc1.w);
        }
    }

    // merge the two halves via smem
    if (half == 1) {
        sAcc[nslot][lane][0] = acc0;
        sAcc[nslot][lane][1] = acc1;
        sM[nslot][lane] = m;
        sS[nslot][lane] = ssum;
    }
    __syncthreads();
    if (half == 0) {
        float m1 = sM[nslot][lane];
        float s1v = sS[nslot][lane];
        float4 o0 = sAcc[nslot][lane][0];
        float4 o1 = sAcc[nslot][lane][1];
        float M = fmaxf(m, m1);              // finite: half 0 is never empty
        float e0 = __expf(m - M);
        float e1 = __expf(m1 - M);           // 0 if half 1 empty (m1 = -inf)
        float S = ssum * e0 + s1v * e1;
        acc0.x = acc0.x * e0 + o0.x * e1; acc0.y = acc0.y * e0 + o0.y * e1;
        acc0.z = acc0.z * e0 + o0.z * e1; acc0.w = acc0.w * e0 + o0.w * e1;
        acc1.x = acc1.x * e0 + o1.x * e1; acc1.y = acc1.y * e0 + o1.y * e1;
        acc1.z = acc1.z * e0 + o1.z * e1; acc1.w = acc1.w * e0 + o1.w * e1;

        float inv = 1.0f / (S + EPSS);
        const float4* pb = (const float4*)(bias + c);
        float4 b0 = pb[0], b1 = pb[1];
        float v[8] = { acc0.x * inv + b0.x, acc0.y * inv + b0.y,
                       acc0.z * inv + b0.z, acc0.w * inv + b0.w,
                       acc1.x * inv + b1.x, acc1.y * inv + b1.y,
                       acc1.z * inv + b1.z, acc1.w * inv + b1.w };
        if (LAYER == 1) {
            #pragma unroll
            for (int j = 0; j < 8; j++) v[j] = v[j] > 0.0f ? v[j] : expm1f(v[j]);
        }
        float* outp = (LAYER == 1) ? g_h : out_arg;
        float4* po = (float4*)(outp + node * CH + c);
        po[0] = make_float4(v[0], v[1], v[2], v[3]);
        po[1] = make_float4(v[4], v[5], v[6], v[7]);
    }
}

// ================= launcher =================================================
extern "C" void kernel_launch(void* const* d_in, const int* in_sizes, int n_in,
                              void* d_out, int out_size) {
    const float* x     = (const float*)d_in[0];
    const int*   ei    = (const int*)  d_in[1];
    const float* W_l1  = (const float*)d_in[2];
    const float* b_l1  = (const float*)d_in[3];
    const float* W_r1  = (const float*)d_in[4];
    const float* b_r1  = (const float*)d_in[5];
    const float* att1  = (const float*)d_in[6];
    const float* bias1 = (const float*)d_in[7];
    const float* W_l2  = (const float*)d_in[8];
    const float* b_l2  = (const float*)d_in[9];
    const float* W_r2  = (const float*)d_in[10];
    const float* b_r2  = (const float*)d_in[11];
    const float* att2  = (const float*)d_in[12];
    const float* bias2 = (const float*)d_in[13];
    float* out = (float*)d_out;

    const int T = 256;
    int blkN    = (NN + T - 1) / T;
    int blkE    = (ETOT + T - 1) / T;
    int blkNode = NN / 4;              // 2 warps per node, 4 nodes/block (exact)
    int blkG1   = (NN + 63) / 64;
    int blkScan = (NN + 1023) / 1024;  // 49

    // CSR build
    zero_deg<<<blkN, T>>>();
    csr_count<<<blkE, T>>>(ei);
    scan1<<<blkScan, 1024>>>();
    scan2<<<1, 64>>>(blkScan);
    scan3<<<blkScan, 1024>>>();
    csr_scatter<<<blkE, T>>>(ei);

    // layer 1
    gemm1_kernel<<<blkG1, T>>>(x, W_l1, b_l1, W_r1, b_r1);
    fused_edge<1><<<blkNode, T>>>(att1, bias1, nullptr);

    // layer 2
    dim3 g2((NN + 127) / 128, 4);
    gemm_dual<<<g2, T>>>(W_l2, b_l2, W_r2, b_r2);
    fused_edge<2><<<blkNode, T>>>(att2, bias2, out);
}